// round 3
// baseline (speedup 1.0000x reference)
#include <cuda_runtime.h>
#include <cuda_bf16.h>

#define N_STEPS   256
#define N_LORS    65536
#define IMG_ELEMS (128*128*128)

// Scratch: image and accumulator in sector-tiled (2x2x2 cube) layout.
// Each 32B sector = one 2x2x2 voxel cube.
__device__ float g_img_cube[IMG_ELEMS];
__device__ float g_acc_cube[IMG_ELEMS];

// cube-layout flat index from voxel coords
__device__ __forceinline__ int cube_flat(int ix, int iy, int iz) {
    const int c = (((ix >> 1) << 6) + (iy >> 1)) * 64 + (iz >> 1);
    return (c << 3) + ((ix & 1) << 2) + ((iy & 1) << 1) + (iz & 1);
}

// ---------------------------------------------------------------------------
// Kernel 1: remap image -> cube layout, zero accumulator
// ---------------------------------------------------------------------------
__global__ void remap_kernel(const float* __restrict__ img) {
    const int i = blockIdx.x * blockDim.x + threadIdx.x;   // linear voxel id
    const int ix = i >> 14, iy = (i >> 7) & 127, iz = i & 127;
    g_img_cube[cube_flat(ix, iy, iz)] = img[i];
    g_acc_cube[i] = 0.f;
}

// ---------------------------------------------------------------------------
// Kernel 2: warp-per-LOR forward + back projection.
//   8 iterations x 32 consecutive steps (lane = step within chunk), so one
//   warp load instruction touches only ~4-6 sectors in the cube layout.
//   Backprojection aggregates same-voxel lanes with __match_any_sync.
// ---------------------------------------------------------------------------
__global__ __launch_bounds__(256)
void trace_kernel(const float* __restrict__ xl,
                  const float* __restrict__ yl,
                  const float* __restrict__ zl) {
    const int warp = blockIdx.x * (blockDim.x >> 5) + (threadIdx.x >> 5);
    const int lane = threadIdx.x & 31;
    const int set  = warp >> 16;          // 0,1,2
    const int lor  = warp & (N_LORS - 1);

    const float* lors = (set == 0) ? xl : (set == 1) ? yl : zl;
    const float* L = lors + 7 * lor;

    const float p1x = L[0], p1y = L[1], p1z = L[2];
    const float dx = __fadd_rn(L[3], -p1x);
    const float dy = __fadd_rn(L[4], -p1y);
    const float dz = __fadd_rn(L[5], -p1z);
    const float meas = L[6];
    const float seg = sqrtf(dx*dx + dy*dy + dz*dz) * (1.0f / N_STEPS);

    int   flats[8];
    float s = 0.f;

    #pragma unroll
    for (int it = 0; it < 8; it++) {
        const int   st = it * 32 + lane;          // consecutive steps per warp
        const float t  = ((float)st + 0.5f) * (1.0f / N_STEPS);
        // pos = p1 + t*d, separate mul/add (no FMA) to match jax exactly
        const float px = __fadd_rn(p1x, __fmul_rn(t, dx));
        const float py = __fadd_rn(p1y, __fmul_rn(t, dy));
        const float pz = __fadd_rn(p1z, __fmul_rn(t, dz));
        // idx = floor((pos+150)/2.34375), IEEE division to match jax
        const float fx = floorf(__fdiv_rn(__fadd_rn(px, 150.0f), 2.34375f));
        const float fy = floorf(__fdiv_rn(__fadd_rn(py, 150.0f), 2.34375f));
        const float fz = floorf(__fdiv_rn(__fadd_rn(pz, 150.0f), 2.34375f));
        const bool inb = (fx >= 0.f) && (fx < 128.f) &&
                         (fy >= 0.f) && (fy < 128.f) &&
                         (fz >= 0.f) && (fz < 128.f);
        int flat = -1;
        if (inb) flat = cube_flat((int)fx, (int)fy, (int)fz);
        flats[it] = flat;
        s += (flat >= 0) ? __ldg(g_img_cube + flat) : 0.f;
    }

    // warp reduction of forward projection
    #pragma unroll
    for (int o = 16; o > 0; o >>= 1)
        s += __shfl_xor_sync(0xffffffffu, s, o);

    const float proj = s * seg;
    const float w = meas / (proj + 1e-8f) * seg;   // ratio * seg

    // backproject: aggregate same-voxel lanes within each 32-step chunk
    #pragma unroll
    for (int it = 0; it < 8; it++) {
        const int f = flats[it];
        const unsigned mask = __match_any_sync(0xffffffffu, f);
        const int leader = __ffs(mask) - 1;
        if (lane == leader && f >= 0) {
            const int cnt = __popc(mask);
            atomicAdd(g_acc_cube + f, w * (float)cnt);
        }
    }
}

// ---------------------------------------------------------------------------
// Kernel 3: out = image / (eff + eps) * acc   (gather from cube layout)
// ---------------------------------------------------------------------------
__global__ void finalize_kernel(const float* __restrict__ img,
                                const float* __restrict__ eff,
                                float* __restrict__ out) {
    const int i = blockIdx.x * blockDim.x + threadIdx.x;
    const int ix = i >> 14, iy = (i >> 7) & 127, iz = i & 127;
    const float a = g_acc_cube[cube_flat(ix, iy, iz)];
    out[i] = img[i] / (eff[i] + 1e-8f) * a;
}

extern "C" void kernel_launch(void* const* d_in, const int* in_sizes, int n_in,
                              void* d_out, int out_size) {
    const float* image = (const float*)d_in[0];
    const float* eff   = (const float*)d_in[1];
    const float* xl    = (const float*)d_in[2];
    const float* yl    = (const float*)d_in[3];
    const float* zl    = (const float*)d_in[4];
    float* out = (float*)d_out;

    remap_kernel<<<IMG_ELEMS / 256, 256>>>(image);

    const int total_warps = 3 * N_LORS;          // one warp per LOR
    trace_kernel<<<total_warps / 8, 256>>>(xl, yl, zl);

    finalize_kernel<<<IMG_ELEMS / 256, 256>>>(image, eff, out);
}